// round 1
// baseline (speedup 1.0000x reference)
#include <cuda_runtime.h>
#include <cuda_bf16.h>

#define BS   8
#define SEQ  2048
#define DIN  2048
#define DOUT 2048
#define RK   8
#define SCALING 2.0f   // 16.0 / R

// Scratch (allocation-free rule: __device__ globals)
__device__ float g_At[BS][DIN * RK];    // [b][d*8 + r]  (A transposed for vector loads)
__device__ float g_Bm[BS][RK * DOUT];   // [b][r*2048 + o]
__device__ float g_xa[BS][SEQ * RK];    // [b][s*8 + r]

// ---------------------------------------------------------------------------
// Kernel 1: gate MLP (recomputed per CTA, tiny) + fill At and B slices.
// grid (16, 8) x 256 threads: each CTA fills 1024 elements of At and of B.
// ---------------------------------------------------------------------------
__global__ __launch_bounds__(256) void k_gate_ab(
    const float* __restrict__ ctr, const float* __restrict__ gamma,
    const float* __restrict__ beta, const float* __restrict__ W1,
    const float* __restrict__ b1, const float* __restrict__ W2,
    const float* __restrict__ b2, const float* __restrict__ Wa,
    const float* __restrict__ Wb)
{
    __shared__ float z[32];
    __shared__ float h[60];
    __shared__ float graw[4];
    __shared__ float gs[4];

    const int b = blockIdx.y;
    const int tid = threadIdx.x;

    if (tid < 32) {
        float v = ctr[b * 32 + tid];
        float s = v;
        #pragma unroll
        for (int o = 16; o; o >>= 1) s += __shfl_xor_sync(0xffffffffu, s, o);
        float mu = s * (1.0f / 32.0f);
        float dv = v - mu;
        float s2 = dv * dv;
        #pragma unroll
        for (int o = 16; o; o >>= 1) s2 += __shfl_xor_sync(0xffffffffu, s2, o);
        float var = s2 * (1.0f / 32.0f);
        z[tid] = dv * rsqrtf(var + 1e-5f) * gamma[tid] + beta[tid];
    }
    __syncthreads();
    if (tid < 60) {
        float s = b1[tid];
        #pragma unroll 8
        for (int c = 0; c < 32; c++) s = fmaf(z[c], W1[tid * 32 + c], s);
        h[tid] = fmaxf(s, 0.0f);
    }
    __syncthreads();
    if (tid < 4) {
        float s = b2[tid];
        for (int j = 0; j < 60; j++) s = fmaf(h[j], W2[tid * 60 + j], s);
        graw[tid] = s;
    }
    __syncthreads();
    if (tid < 4) {
        float m = fmaxf(fmaxf(graw[0], graw[1]), fmaxf(graw[2], graw[3]));
        float den = expf(graw[0] - m) + expf(graw[1] - m) +
                    expf(graw[2] - m) + expf(graw[3] - m);
        gs[tid] = expf(graw[tid] - m) / den;
    }
    __syncthreads();

    const float g0 = gs[0], g1 = gs[1], g2 = gs[2], g3 = gs[3];

    const int e0 = blockIdx.x * 1024 + tid * 4;
    float v[4];
    // At[b][d*8+r] = sum_c gate[c] * Wa[(r*DIN + d)*4 + c]
    #pragma unroll
    for (int k = 0; k < 4; k++) {
        int e = e0 + k;
        int d = e >> 3, r = e & 7;
        float4 w = *(const float4*)(Wa + (size_t)(r * DIN + d) * 4);
        v[k] = g0 * w.x + g1 * w.y + g2 * w.z + g3 * w.w;
    }
    *(float4*)(&g_At[b][e0]) = make_float4(v[0], v[1], v[2], v[3]);

    // B[b][e] = sum_c gate[c] * Wb[e*4 + c]   (e = r*DOUT + o directly)
    #pragma unroll
    for (int k = 0; k < 4; k++) {
        int e = e0 + k;
        float4 w = *(const float4*)(Wb + (size_t)e * 4);
        v[k] = g0 * w.x + g1 * w.y + g2 * w.z + g3 * w.w;
    }
    *(float4*)(&g_Bm[b][e0]) = make_float4(v[0], v[1], v[2], v[3]);
}

// ---------------------------------------------------------------------------
// Kernel 2: xa[b][s][r] = sum_d x[b][s][d] * A[b][r][d]
// 256 threads: thread owns dims [tid*8, tid*8+8), A in registers (64 f32),
// 4 rows/iter, multi-value butterfly reduce (lane l ends with combo l),
// cross-warp reduce via double-buffered smem, 1 barrier per iteration.
// ---------------------------------------------------------------------------
__global__ __launch_bounds__(256, 1) void k_xa(const float* __restrict__ x)
{
    const int b = blockIdx.y;
    const int tid = threadIdx.x;
    const int warp = tid >> 5, lane = tid & 31;
    const int d0 = tid * 8;

    float a_reg[8][8];  // [j (dim within thread)][r]
    {
        const float* At = g_At[b];
        #pragma unroll
        for (int j = 0; j < 8; j++) {
            float4 lo = *(const float4*)(At + (size_t)(d0 + j) * 8);
            float4 hi = *(const float4*)(At + (size_t)(d0 + j) * 8 + 4);
            a_reg[j][0] = lo.x; a_reg[j][1] = lo.y; a_reg[j][2] = lo.z; a_reg[j][3] = lo.w;
            a_reg[j][4] = hi.x; a_reg[j][5] = hi.y; a_reg[j][6] = hi.z; a_reg[j][7] = hi.w;
        }
    }

    __shared__ float part[2][8][32];
    const float* xb = x + (size_t)b * SEQ * DIN;

    int buf = 0;
    for (int q = blockIdx.x; q < SEQ / 4; q += gridDim.x, buf ^= 1) {
        const int s = q * 4;

        float4 xv[4][2];
        #pragma unroll
        for (int rr = 0; rr < 4; rr++) {
            const float* xp = xb + (size_t)(s + rr) * DIN + d0;
            xv[rr][0] = *(const float4*)xp;
            xv[rr][1] = *(const float4*)(xp + 4);
        }

        float acc[32];  // index = rr*8 + r
        #pragma unroll
        for (int i = 0; i < 32; i++) acc[i] = 0.0f;

        #pragma unroll
        for (int rr = 0; rr < 4; rr++) {
            const float* xr = (const float*)xv[rr];
            #pragma unroll
            for (int j = 0; j < 8; j++) {
                float xj = xr[j];
                #pragma unroll
                for (int r = 0; r < 8; r++)
                    acc[rr * 8 + r] = fmaf(xj, a_reg[j][r], acc[rr * 8 + r]);
            }
        }

        // Multi-value butterfly: reduce 32 values over 32 lanes;
        // after all steps, lane l holds the warp-total of value index l.
        #pragma unroll
        for (int off = 16; off >= 1; off >>= 1) {
            const bool up = (lane & off) != 0;
            #pragma unroll
            for (int i = 0; i < off; i++) {
                float send = up ? acc[i] : acc[off + i];
                float recv = __shfl_xor_sync(0xffffffffu, send, off);
                acc[i] = (up ? acc[off + i] : acc[i]) + recv;
            }
        }

        part[buf][warp][lane] = acc[0];
        __syncthreads();
        if (tid < 32) {
            float sum = 0.0f;
            #pragma unroll
            for (int w = 0; w < 8; w++) sum += part[buf][w][tid];
            int row = s + (tid >> 3);
            g_xa[b][row * 8 + (tid & 7)] = sum;
        }
        // next iter uses the other buffer; safe with a single barrier per iter
    }
}

// ---------------------------------------------------------------------------
// Kernel 3: out[b][s][o] = SCALING * sum_r xa[b][s][r] * B[b][r][o]
// B in registers, xa rows are 32-byte broadcast loads, pure streaming stores.
// ---------------------------------------------------------------------------
__global__ __launch_bounds__(256, 2) void k_out(float* __restrict__ out)
{
    const int b = blockIdx.y;
    const int tid = threadIdx.x;
    const int d0 = tid * 8;

    float breg[8][8];  // [r][j]
    {
        const float* Bm = g_Bm[b];
        #pragma unroll
        for (int r = 0; r < 8; r++) {
            float4 lo = *(const float4*)(Bm + (size_t)r * DOUT + d0);
            float4 hi = *(const float4*)(Bm + (size_t)r * DOUT + d0 + 4);
            breg[r][0] = lo.x; breg[r][1] = lo.y; breg[r][2] = lo.z; breg[r][3] = lo.w;
            breg[r][4] = hi.x; breg[r][5] = hi.y; breg[r][6] = hi.z; breg[r][7] = hi.w;
        }
    }

    float* ob = out + (size_t)b * SEQ * DOUT;
    const float* xab = g_xa[b];

    for (int q = blockIdx.x; q < SEQ / 4; q += gridDim.x) {
        const int s = q * 4;
        float4 xav[4][2];
        #pragma unroll
        for (int rr = 0; rr < 4; rr++) {
            xav[rr][0] = *(const float4*)(xab + (size_t)(s + rr) * 8);
            xav[rr][1] = *(const float4*)(xab + (size_t)(s + rr) * 8 + 4);
        }
        #pragma unroll
        for (int rr = 0; rr < 4; rr++) {
            const float* xar = (const float*)xav[rr];
            float o[8];
            #pragma unroll
            for (int j = 0; j < 8; j++) o[j] = 0.0f;
            #pragma unroll
            for (int r = 0; r < 8; r++) {
                float xv = xar[r];
                #pragma unroll
                for (int j = 0; j < 8; j++)
                    o[j] = fmaf(xv, breg[r][j], o[j]);
            }
            float* op = ob + (size_t)(s + rr) * DOUT + d0;
            *(float4*)op       = make_float4(o[0] * SCALING, o[1] * SCALING,
                                             o[2] * SCALING, o[3] * SCALING);
            *(float4*)(op + 4) = make_float4(o[4] * SCALING, o[5] * SCALING,
                                             o[6] * SCALING, o[7] * SCALING);
        }
    }
}

// ---------------------------------------------------------------------------
extern "C" void kernel_launch(void* const* d_in, const int* in_sizes, int n_in,
                              void* d_out, int out_size)
{
    const float* x     = (const float*)d_in[0];
    const float* ctr   = (const float*)d_in[1];
    const float* gamma = (const float*)d_in[2];
    const float* beta  = (const float*)d_in[3];
    const float* W1    = (const float*)d_in[4];
    const float* b1    = (const float*)d_in[5];
    const float* W2    = (const float*)d_in[6];
    const float* b2    = (const float*)d_in[7];
    const float* Wa    = (const float*)d_in[8];
    const float* Wb    = (const float*)d_in[9];
    float* out = (float*)d_out;

    k_gate_ab<<<dim3(16, 8), 256>>>(ctr, gamma, beta, W1, b1, W2, b2, Wa, Wb);
    k_xa<<<dim3(18, 8), 256>>>(x);
    k_out<<<dim3(36, 8), 256>>>(out);
}

// round 2
// speedup vs baseline: 1.2901x; 1.2901x over previous
#include <cuda_runtime.h>
#include <cuda_bf16.h>

#define BS   8
#define SEQ  2048
#define DIN  2048
#define DOUT 2048
#define RK   8
#define SCALING 2.0f   // 16.0 / R

typedef unsigned long long u64;

// Scratch (allocation-free rule: __device__ globals)
__device__ float g_gate[BS][4];
__device__ float g_At[BS][DIN * RK];    // [b][d*8 + r]
__device__ float g_Bm[BS][RK * DOUT];   // [b][r*2048 + o]

// ---- f32x2 packed-math helpers (sm_100+) -----------------------------------
__device__ __forceinline__ u64 ffma2(u64 a, u64 b, u64 c) {
    u64 d;
    asm("fma.rn.f32x2 %0, %1, %2, %3;" : "=l"(d) : "l"(a), "l"(b), "l"(c));
    return d;
}
__device__ __forceinline__ u64 rep2(float x) {
    u64 r; asm("mov.b64 %0, {%1, %1};" : "=l"(r) : "f"(x)); return r;
}
__device__ __forceinline__ u64 pk2(float lo, float hi) {
    u64 r; asm("mov.b64 %0, {%1, %2};" : "=l"(r) : "f"(lo), "f"(hi)); return r;
}
__device__ __forceinline__ void upk2(u64 v, float& lo, float& hi) {
    asm("mov.b64 {%0, %1}, %2;" : "=f"(lo), "=f"(hi) : "l"(v));
}

// ---------------------------------------------------------------------------
// Kernel 1: gate MLP, computed ONCE. 1 CTA, warp w = batch w.
// ---------------------------------------------------------------------------
__global__ __launch_bounds__(256) void k_gate(
    const float* __restrict__ ctr, const float* __restrict__ gamma,
    const float* __restrict__ beta, const float* __restrict__ W1,
    const float* __restrict__ b1, const float* __restrict__ W2,
    const float* __restrict__ b2)
{
    const int warp = threadIdx.x >> 5, lane = threadIdx.x & 31;
    const int b = warp;

    float v = ctr[b * 32 + lane];
    float s = v;
    #pragma unroll
    for (int o = 16; o; o >>= 1) s += __shfl_xor_sync(0xffffffffu, s, o);
    float mu = s * (1.0f / 32.0f);
    float dv = v - mu;
    float s2 = dv * dv;
    #pragma unroll
    for (int o = 16; o; o >>= 1) s2 += __shfl_xor_sync(0xffffffffu, s2, o);
    float z = dv * rsqrtf(s2 * (1.0f / 32.0f) + 1e-5f) * gamma[lane] + beta[lane];

    // h[60]: lane computes neurons (lane) and (lane+32 if <60)
    float ha = b1[lane];
    float hb = (lane < 28) ? b1[lane + 32] : 0.0f;
    #pragma unroll
    for (int c = 0; c < 32; c++) {
        float zc = __shfl_sync(0xffffffffu, z, c);
        ha = fmaf(zc, W1[lane * 32 + c], ha);
        if (lane < 28) hb = fmaf(zc, W1[(lane + 32) * 32 + c], hb);
    }
    ha = fmaxf(ha, 0.0f);
    hb = fmaxf(hb, 0.0f);

    float g[4];
    #pragma unroll
    for (int t = 0; t < 4; t++) {
        float p = ha * W2[t * 60 + lane];
        if (lane < 28) p = fmaf(hb, W2[t * 60 + lane + 32], p);
        #pragma unroll
        for (int o = 16; o; o >>= 1) p += __shfl_xor_sync(0xffffffffu, p, o);
        g[t] = p + b2[t];
    }
    if (lane == 0) {
        float m = fmaxf(fmaxf(g[0], g[1]), fmaxf(g[2], g[3]));
        float e0 = expf(g[0] - m), e1 = expf(g[1] - m),
              e2 = expf(g[2] - m), e3 = expf(g[3] - m);
        float inv = 1.0f / (e0 + e1 + e2 + e3);
        g_gate[b][0] = e0 * inv; g_gate[b][1] = e1 * inv;
        g_gate[b][2] = e2 * inv; g_gate[b][3] = e3 * inv;
    }
}

// ---------------------------------------------------------------------------
// Kernel 2: streaming fill of At and B from the 4 gate weights.
// ---------------------------------------------------------------------------
__global__ __launch_bounds__(256) void k_fill(
    const float* __restrict__ Wa, const float* __restrict__ Wb)
{
    const int b = blockIdx.y;
    const int tid = threadIdx.x;
    const float g0 = g_gate[b][0], g1 = g_gate[b][1],
                g2 = g_gate[b][2], g3 = g_gate[b][3];

    const int e0 = blockIdx.x * 1024 + tid * 4;
    float v[4];
    #pragma unroll
    for (int k = 0; k < 4; k++) {
        int e = e0 + k;
        int d = e >> 3, r = e & 7;
        float4 w = *(const float4*)(Wa + (size_t)(r * DIN + d) * 4);
        v[k] = g0 * w.x + g1 * w.y + g2 * w.z + g3 * w.w;
    }
    *(float4*)(&g_At[b][e0]) = make_float4(v[0], v[1], v[2], v[3]);

    #pragma unroll
    for (int k = 0; k < 4; k++) {
        int e = e0 + k;
        float4 w = *(const float4*)(Wb + (size_t)e * 4);
        v[k] = g0 * w.x + g1 * w.y + g2 * w.z + g3 * w.w;
    }
    *(float4*)(&g_Bm[b][e0]) = make_float4(v[0], v[1], v[2], v[3]);
}

// ---------------------------------------------------------------------------
// Kernel 3 (fused): out[b][s][:] = SCALING * (x[b][s][:] @ A^T) @ B
// Thread owns dims [tid*8, tid*8+8). A,B in registers, packed for f32x2.
// Per iter: 4 rows. Phase 1: xa via FFMA2 + multi-value butterfly + smem.
// Phase 2: out via FFMA2 from broadcast xa. Next-iter x prefetched between.
// ---------------------------------------------------------------------------
__global__ __launch_bounds__(256, 1) void k_main(
    const float* __restrict__ x, float* __restrict__ out)
{
    const int b = blockIdx.y;
    const int tid = threadIdx.x;
    const int warp = tid >> 5, lane = tid & 31;
    const int d0 = tid * 8;

    // A packed: a2[j][rp] = { At[d0+j][rp], At[d0+j][rp+4] }
    u64 a2[8][4];
    {
        const float* At = g_At[b];
        #pragma unroll
        for (int j = 0; j < 8; j++) {
            float4 lo = *(const float4*)(At + (size_t)(d0 + j) * 8);
            float4 hi = *(const float4*)(At + (size_t)(d0 + j) * 8 + 4);
            a2[j][0] = pk2(lo.x, hi.x); a2[j][1] = pk2(lo.y, hi.y);
            a2[j][2] = pk2(lo.z, hi.z); a2[j][3] = pk2(lo.w, hi.w);
        }
    }
    // B packed: b2[r][jp] = { B[r][d0+jp], B[r][d0+jp+4] }
    u64 b2[8][4];
    {
        const float* Bm = g_Bm[b];
        #pragma unroll
        for (int r = 0; r < 8; r++) {
            float4 lo = *(const float4*)(Bm + (size_t)r * DOUT + d0);
            float4 hi = *(const float4*)(Bm + (size_t)r * DOUT + d0 + 4);
            b2[r][0] = pk2(lo.x, hi.x); b2[r][1] = pk2(lo.y, hi.y);
            b2[r][2] = pk2(lo.z, hi.z); b2[r][3] = pk2(lo.w, hi.w);
        }
    }

    __shared__ float part[8][32];
    __shared__ float xa_s[32];   // [local_row*8 + r], pre-scaled by SCALING

    const float* xb = x + (size_t)b * SEQ * DIN;
    float* ob = out + (size_t)b * SEQ * DOUT;
    const int step = gridDim.x;

    // initial load
    float4 xv[4][2];
    int q = blockIdx.x;
    {
        const int s = q * 4;
        #pragma unroll
        for (int rr = 0; rr < 4; rr++) {
            const float* xp = xb + (size_t)(s + rr) * DIN + d0;
            xv[rr][0] = *(const float4*)xp;
            xv[rr][1] = *(const float4*)(xp + 4);
        }
    }

    for (; q < SEQ / 4; q += step) {
        const int s = q * 4;

        // ---- phase 1: xa accumulation (packed over (r, r+4)) ----
        u64 acc2[4][4];
        #pragma unroll
        for (int rr = 0; rr < 4; rr++)
            #pragma unroll
            for (int rp = 0; rp < 4; rp++) acc2[rr][rp] = 0ull;

        #pragma unroll
        for (int rr = 0; rr < 4; rr++) {
            const float* xr = (const float*)xv[rr];
            #pragma unroll
            for (int j = 0; j < 8; j++) {
                u64 xj2 = rep2(xr[j]);
                #pragma unroll
                for (int rp = 0; rp < 4; rp++)
                    acc2[rr][rp] = ffma2(xj2, a2[j][rp], acc2[rr][rp]);
            }
        }

        // prefetch next iteration's rows (xv now dead)
        const int qn = q + step;
        if (qn < SEQ / 4) {
            const int sn = qn * 4;
            #pragma unroll
            for (int rr = 0; rr < 4; rr++) {
                const float* xp = xb + (size_t)(sn + rr) * DIN + d0;
                xv[rr][0] = *(const float4*)xp;
                xv[rr][1] = *(const float4*)(xp + 4);
            }
        }

        // unpack to 32 scalars: acc[rr*8 + r]
        float acc[32];
        #pragma unroll
        for (int rr = 0; rr < 4; rr++)
            #pragma unroll
            for (int rp = 0; rp < 4; rp++)
                upk2(acc2[rr][rp], acc[rr * 8 + rp], acc[rr * 8 + rp + 4]);

        // multi-value butterfly: lane l ends with warp-total of value l
        #pragma unroll
        for (int off = 16; off >= 1; off >>= 1) {
            const bool up = (lane & off) != 0;
            #pragma unroll
            for (int i = 0; i < off; i++) {
                float send = up ? acc[i] : acc[off + i];
                float recv = __shfl_xor_sync(0xffffffffu, send, off);
                acc[i] = (up ? acc[off + i] : acc[i]) + recv;
            }
        }

        part[warp][lane] = acc[0];
        __syncthreads();
        if (tid < 32) {
            float sum = 0.0f;
            #pragma unroll
            for (int w = 0; w < 8; w++) sum += part[w][tid];
            xa_s[tid] = sum * SCALING;
        }
        __syncthreads();

        // ---- phase 2: out rows, packed over (j, j+4) ----
        #pragma unroll
        for (int rr = 0; rr < 4; rr++) {
            u64 o2[4];
            #pragma unroll
            for (int jp = 0; jp < 4; jp++) o2[jp] = 0ull;
            #pragma unroll
            for (int r = 0; r < 8; r++) {
                u64 xs2 = rep2(xa_s[rr * 8 + r]);
                #pragma unroll
                for (int jp = 0; jp < 4; jp++)
                    o2[jp] = ffma2(xs2, b2[r][jp], o2[jp]);
            }
            float o[8];
            #pragma unroll
            for (int jp = 0; jp < 4; jp++) upk2(o2[jp], o[jp], o[jp + 4]);
            float* op = ob + (size_t)(s + rr) * DOUT + d0;
            *(float4*)op       = make_float4(o[0], o[1], o[2], o[3]);
            *(float4*)(op + 4) = make_float4(o[4], o[5], o[6], o[7]);
        }
    }
}

// ---------------------------------------------------------------------------
extern "C" void kernel_launch(void* const* d_in, const int* in_sizes, int n_in,
                              void* d_out, int out_size)
{
    const float* x     = (const float*)d_in[0];
    const float* ctr   = (const float*)d_in[1];
    const float* gamma = (const float*)d_in[2];
    const float* beta  = (const float*)d_in[3];
    const float* W1    = (const float*)d_in[4];
    const float* b1    = (const float*)d_in[5];
    const float* W2    = (const float*)d_in[6];
    const float* b2    = (const float*)d_in[7];
    const float* Wa    = (const float*)d_in[8];
    const float* Wb    = (const float*)d_in[9];
    float* out = (float*)d_out;

    k_gate<<<1, 256>>>(ctr, gamma, beta, W1, b1, W2, b2);
    k_fill<<<dim3(16, 8), 256>>>(Wa, Wb);
    k_main<<<dim3(18, 8), 256>>>(x, out);
}

// round 3
// speedup vs baseline: 1.4482x; 1.1226x over previous
#include <cuda_runtime.h>
#include <cuda_bf16.h>

#define BS   8
#define SEQ  2048
#define DIN  2048
#define DOUT 2048
#define RK   8
#define SCALING 2.0f   // 16.0 / R (folded into g_Bm at fill time)

typedef unsigned long long u64;

// Scratch (allocation-free rule: __device__ globals)
__device__ float g_At[BS][DIN * RK];    // [b][d*8 + r]
__device__ float g_Bm[BS][RK * DOUT];   // [b][r*2048 + o], pre-scaled by SCALING

// ---- f32x2 packed-math helpers (sm_100+) -----------------------------------
__device__ __forceinline__ u64 ffma2(u64 a, u64 b, u64 c) {
    u64 d;
    asm("fma.rn.f32x2 %0, %1, %2, %3;" : "=l"(d) : "l"(a), "l"(b), "l"(c));
    return d;
}
__device__ __forceinline__ u64 rep2(float x) {
    u64 r; asm("mov.b64 %0, {%1, %1};" : "=l"(r) : "f"(x)); return r;
}
__device__ __forceinline__ u64 pk2(float lo, float hi) {
    u64 r; asm("mov.b64 %0, {%1, %2};" : "=l"(r) : "f"(lo), "f"(hi)); return r;
}
__device__ __forceinline__ void upk2(u64 v, float& lo, float& hi) {
    asm("mov.b64 {%0, %1}, %2;" : "=f"(lo), "=f"(hi) : "l"(v));
}

// ---------------------------------------------------------------------------
// Kernel 1 (fused gate + fill): warp 0 of each CTA recomputes the tiny gate
// MLP while all threads' Wa/Wb loads are already in flight; after one barrier
// everyone combines and stores At / (SCALING*B).
// grid (16, 8) x 256 threads.
// ---------------------------------------------------------------------------
__global__ __launch_bounds__(256) void k_fill(
    const float* __restrict__ ctr, const float* __restrict__ gamma,
    const float* __restrict__ beta, const float* __restrict__ W1,
    const float* __restrict__ b1, const float* __restrict__ W2,
    const float* __restrict__ b2, const float* __restrict__ Wa,
    const float* __restrict__ Wb)
{
    __shared__ float gs[4];
    const int b = blockIdx.y;
    const int tid = threadIdx.x;

    // ---- issue fill loads first (independent of gate) ----
    const int e0 = blockIdx.x * 1024 + tid * 4;
    const int d  = e0 >> 3;        // e0 % 4 == 0 -> all 4 elems share d
    const int r0 = e0 & 7;         // 0 or 4
    float4 wa[4], wb[4];
    #pragma unroll
    for (int k = 0; k < 4; k++) {
        wa[k] = *(const float4*)(Wa + (size_t)((r0 + k) * DIN + d) * 4);
        wb[k] = *(const float4*)(Wb + (size_t)(e0 + k) * 4);
    }

    // ---- warp 0: gate MLP for batch b ----
    if (tid < 32) {
        const int lane = tid;
        float v = ctr[b * 32 + lane];
        float s = v;
        #pragma unroll
        for (int o = 16; o; o >>= 1) s += __shfl_xor_sync(0xffffffffu, s, o);
        float mu = s * (1.0f / 32.0f);
        float dv = v - mu;
        float s2 = dv * dv;
        #pragma unroll
        for (int o = 16; o; o >>= 1) s2 += __shfl_xor_sync(0xffffffffu, s2, o);
        float z = dv * rsqrtf(s2 * (1.0f / 32.0f) + 1e-5f) * gamma[lane] + beta[lane];

        float ha = b1[lane];
        float hb = (lane < 28) ? b1[lane + 32] : 0.0f;
        #pragma unroll
        for (int c = 0; c < 32; c++) {
            float zc = __shfl_sync(0xffffffffu, z, c);
            ha = fmaf(zc, W1[lane * 32 + c], ha);
            if (lane < 28) hb = fmaf(zc, W1[(lane + 32) * 32 + c], hb);
        }
        ha = fmaxf(ha, 0.0f);
        hb = fmaxf(hb, 0.0f);

        float g[4];
        #pragma unroll
        for (int t = 0; t < 4; t++) {
            float p = ha * W2[t * 60 + lane];
            if (lane < 28) p = fmaf(hb, W2[t * 60 + lane + 32], p);
            #pragma unroll
            for (int o = 16; o; o >>= 1) p += __shfl_xor_sync(0xffffffffu, p, o);
            g[t] = p + b2[t];
        }
        if (lane == 0) {
            float m = fmaxf(fmaxf(g[0], g[1]), fmaxf(g[2], g[3]));
            float e0v = expf(g[0] - m), e1v = expf(g[1] - m),
                  e2v = expf(g[2] - m), e3v = expf(g[3] - m);
            float inv = 1.0f / (e0v + e1v + e2v + e3v);
            gs[0] = e0v * inv; gs[1] = e1v * inv;
            gs[2] = e2v * inv; gs[3] = e3v * inv;
        }
    }
    __syncthreads();

    const float g0 = gs[0], g1 = gs[1], g2 = gs[2], g3 = gs[3];
    float v[4];
    #pragma unroll
    for (int k = 0; k < 4; k++)
        v[k] = g0 * wa[k].x + g1 * wa[k].y + g2 * wa[k].z + g3 * wa[k].w;
    *(float4*)(&g_At[b][e0]) = make_float4(v[0], v[1], v[2], v[3]);

    #pragma unroll
    for (int k = 0; k < 4; k++)
        v[k] = SCALING * (g0 * wb[k].x + g1 * wb[k].y + g2 * wb[k].z + g3 * wb[k].w);
    *(float4*)(&g_Bm[b][e0]) = make_float4(v[0], v[1], v[2], v[3]);
}

// ---------------------------------------------------------------------------
// Kernel 2 (fused main): out[b][s][:] = (x[b][s][:] @ A^T) @ (SCALING*B)
// Thread owns dims [tid*8, tid*8+8). A,B in registers, f32x2 packed math.
// Per iter: 4 rows. One barrier per iter, double-buffered partials, warp-
// replicated cross-warp reduce, shfl-broadcast into phase 2. Streaming ld/st.
// ---------------------------------------------------------------------------
__global__ __launch_bounds__(256, 1) void k_main(
    const float* __restrict__ x, float* __restrict__ out)
{
    const int b = blockIdx.y;
    const int tid = threadIdx.x;
    const int warp = tid >> 5, lane = tid & 31;
    const int d0 = tid * 8;

    // A packed: a2[j][rp] = { At[d0+j][rp], At[d0+j][rp+4] }
    u64 a2[8][4];
    {
        const float* At = g_At[b];
        #pragma unroll
        for (int j = 0; j < 8; j++) {
            float4 lo = *(const float4*)(At + (size_t)(d0 + j) * 8);
            float4 hi = *(const float4*)(At + (size_t)(d0 + j) * 8 + 4);
            a2[j][0] = pk2(lo.x, hi.x); a2[j][1] = pk2(lo.y, hi.y);
            a2[j][2] = pk2(lo.z, hi.z); a2[j][3] = pk2(lo.w, hi.w);
        }
    }
    // B packed (pre-scaled): b2r[r][jp] = { B[r][d0+jp], B[r][d0+jp+4] }
    u64 b2r[8][4];
    {
        const float* Bm = g_Bm[b];
        #pragma unroll
        for (int r = 0; r < 8; r++) {
            float4 lo = *(const float4*)(Bm + (size_t)r * DOUT + d0);
            float4 hi = *(const float4*)(Bm + (size_t)r * DOUT + d0 + 4);
            b2r[r][0] = pk2(lo.x, hi.x); b2r[r][1] = pk2(lo.y, hi.y);
            b2r[r][2] = pk2(lo.z, hi.z); b2r[r][3] = pk2(lo.w, hi.w);
        }
    }

    __shared__ float part[2][8][32];

    const float* xb = x + (size_t)b * SEQ * DIN;
    float* ob = out + (size_t)b * SEQ * DOUT;
    const int step = gridDim.x;

    float4 xv[4][2];
    int q = blockIdx.x;
    {
        const int s = q * 4;
        #pragma unroll
        for (int rr = 0; rr < 4; rr++) {
            const float* xp = xb + (size_t)(s + rr) * DIN + d0;
            xv[rr][0] = __ldcs((const float4*)xp);
            xv[rr][1] = __ldcs((const float4*)(xp + 4));
        }
    }

    int buf = 0;
    for (; q < SEQ / 4; q += step, buf ^= 1) {
        const int s = q * 4;

        // ---- phase 1: xa accumulation, packed over (r, r+4) ----
        u64 acc2[4][4];
        #pragma unroll
        for (int rr = 0; rr < 4; rr++)
            #pragma unroll
            for (int rp = 0; rp < 4; rp++) acc2[rr][rp] = 0ull;

        #pragma unroll
        for (int rr = 0; rr < 4; rr++) {
            const float* xr = (const float*)xv[rr];
            #pragma unroll
            for (int j = 0; j < 8; j++) {
                u64 xj2 = rep2(xr[j]);
                #pragma unroll
                for (int rp = 0; rp < 4; rp++)
                    acc2[rr][rp] = ffma2(xj2, a2[j][rp], acc2[rr][rp]);
            }
        }

        // prefetch next iteration's rows (xv dead now)
        const int qn = q + step;
        if (qn < SEQ / 4) {
            const int sn = qn * 4;
            #pragma unroll
            for (int rr = 0; rr < 4; rr++) {
                const float* xp = xb + (size_t)(sn + rr) * DIN + d0;
                xv[rr][0] = __ldcs((const float4*)xp);
                xv[rr][1] = __ldcs((const float4*)(xp + 4));
            }
        }

        // unpack to 32 scalars: acc[rr*8 + r]
        float acc[32];
        #pragma unroll
        for (int rr = 0; rr < 4; rr++)
            #pragma unroll
            for (int rp = 0; rp < 4; rp++)
                upk2(acc2[rr][rp], acc[rr * 8 + rp], acc[rr * 8 + rp + 4]);

        // multi-value butterfly: lane l ends with warp-total of value l
        #pragma unroll
        for (int off = 16; off >= 1; off >>= 1) {
            const bool up = (lane & off) != 0;
            #pragma unroll
            for (int i = 0; i < off; i++) {
                float send = up ? acc[i] : acc[off + i];
                float recv = __shfl_xor_sync(0xffffffffu, send, off);
                acc[i] = (up ? acc[off + i] : acc[i]) + recv;
            }
        }

        part[buf][warp][lane] = acc[0];
        __syncthreads();

        // warp-replicated cross-warp sum: lane l of EVERY warp gets xa[l]
        float xa = part[buf][0][lane];
        #pragma unroll
        for (int w = 1; w < 8; w++) xa += part[buf][w][lane];

        // ---- phase 2: out rows, packed over (j, j+4); xa via shfl bcast ----
        #pragma unroll
        for (int rr = 0; rr < 4; rr++) {
            u64 o2[4];
            #pragma unroll
            for (int jp = 0; jp < 4; jp++) o2[jp] = 0ull;
            #pragma unroll
            for (int r = 0; r < 8; r++) {
                float xs = __shfl_sync(0xffffffffu, xa, rr * 8 + r);
                u64 xs2 = rep2(xs);
                #pragma unroll
                for (int jp = 0; jp < 4; jp++)
                    o2[jp] = ffma2(xs2, b2r[r][jp], o2[jp]);
            }
            float o[8];
            #pragma unroll
            for (int jp = 0; jp < 4; jp++) upk2(o2[jp], o[jp], o[jp + 4]);
            float* op = ob + (size_t)(s + rr) * DOUT + d0;
            __stcs((float4*)op,       make_float4(o[0], o[1], o[2], o[3]));
            __stcs((float4*)(op + 4), make_float4(o[4], o[5], o[6], o[7]));
        }
    }
}

// ---------------------------------------------------------------------------
extern "C" void kernel_launch(void* const* d_in, const int* in_sizes, int n_in,
                              void* d_out, int out_size)
{
    const float* x     = (const float*)d_in[0];
    const float* ctr   = (const float*)d_in[1];
    const float* gamma = (const float*)d_in[2];
    const float* beta  = (const float*)d_in[3];
    const float* W1    = (const float*)d_in[4];
    const float* b1    = (const float*)d_in[5];
    const float* W2    = (const float*)d_in[6];
    const float* b2    = (const float*)d_in[7];
    const float* Wa    = (const float*)d_in[8];
    const float* Wb    = (const float*)d_in[9];
    float* out = (float*)d_out;

    k_fill<<<dim3(16, 8), 256>>>(ctr, gamma, beta, W1, b1, W2, b2, Wa, Wb);
    k_main<<<dim3(18, 8), 256>>>(x, out);
}

// round 4
// speedup vs baseline: 1.5556x; 1.0742x over previous
#include <cuda_runtime.h>
#include <cuda_bf16.h>

#define BS   8
#define SEQ  2048
#define DIN  2048
#define DOUT 2048
#define RK   8
#define SCALING 2.0f   // 16.0 / R (folded into g_Bm at fill time)

typedef unsigned long long u64;

// Scratch (allocation-free rule: __device__ globals)
__device__ float g_At[BS][DIN * RK];    // [b][d*8 + r]
__device__ float g_Bm[BS][RK * DOUT];   // [b][r*2048 + o], pre-scaled by SCALING

// ---- f32x2 packed-math helpers (sm_100+) -----------------------------------
__device__ __forceinline__ u64 ffma2(u64 a, u64 b, u64 c) {
    u64 d;
    asm("fma.rn.f32x2 %0, %1, %2, %3;" : "=l"(d) : "l"(a), "l"(b), "l"(c));
    return d;
}
__device__ __forceinline__ u64 rep2(float x) {
    u64 r; asm("mov.b64 %0, {%1, %1};" : "=l"(r) : "f"(x)); return r;
}
__device__ __forceinline__ u64 pk2(float lo, float hi) {
    u64 r; asm("mov.b64 %0, {%1, %2};" : "=l"(r) : "f"(lo), "f"(hi)); return r;
}
__device__ __forceinline__ void upk2(u64 v, float& lo, float& hi) {
    asm("mov.b64 {%0, %1}, %2;" : "=f"(lo), "=f"(hi) : "l"(v));
}

// ---------------------------------------------------------------------------
// Kernel 1 (fused gate + fill). Wa/Wb loads issued first (gate-independent),
// gate MLP computed with 2 warps + smem (short dependency chain), one barrier,
// then combine + store At / (SCALING*B).  grid (16, 8) x 256.
// ---------------------------------------------------------------------------
__global__ __launch_bounds__(256) void k_fill(
    const float* __restrict__ ctr, const float* __restrict__ gamma,
    const float* __restrict__ beta, const float* __restrict__ W1,
    const float* __restrict__ b1, const float* __restrict__ W2,
    const float* __restrict__ b2, const float* __restrict__ Wa,
    const float* __restrict__ Wb)
{
    __shared__ float zs[32];
    __shared__ float hs[64];
    __shared__ float gs[4];
    const int b = blockIdx.y;
    const int tid = threadIdx.x;

    // ---- issue fill loads first ----
    const int e0 = blockIdx.x * 1024 + tid * 4;
    const int d  = e0 >> 3;
    const int r0 = e0 & 7;
    float4 wa[4], wb[4];
    #pragma unroll
    for (int k = 0; k < 4; k++) {
        wa[k] = *(const float4*)(Wa + (size_t)((r0 + k) * DIN + d) * 4);
        wb[k] = *(const float4*)(Wb + (size_t)(e0 + k) * 4);
    }

    // ---- gate MLP ----
    if (tid < 32) {
        float v = ctr[b * 32 + tid];
        float s = v;
        #pragma unroll
        for (int o = 16; o; o >>= 1) s += __shfl_xor_sync(0xffffffffu, s, o);
        float mu = s * (1.0f / 32.0f);
        float dv = v - mu;
        float s2 = dv * dv;
        #pragma unroll
        for (int o = 16; o; o >>= 1) s2 += __shfl_xor_sync(0xffffffffu, s2, o);
        zs[tid] = dv * rsqrtf(s2 * (1.0f / 32.0f) + 1e-5f) * gamma[tid] + beta[tid];
    }
    __syncthreads();
    if (tid < 64) {   // 2 warps, unrolled LDS reads (no serial shfl chain)
        float h = 0.0f;
        if (tid < 60) {
            h = b1[tid];
            #pragma unroll
            for (int c = 0; c < 32; c++) h = fmaf(zs[c], W1[tid * 32 + c], h);
            h = fmaxf(h, 0.0f);
        }
        hs[tid] = h;
    }
    __syncthreads();
    if (tid < 4) {
        float s = b2[tid];
        #pragma unroll
        for (int j = 0; j < 60; j++) s = fmaf(hs[j], W2[tid * 60 + j], s);
        gs[tid] = s;
    }
    __syncthreads();
    if (tid < 4) {
        float m = fmaxf(fmaxf(gs[0], gs[1]), fmaxf(gs[2], gs[3]));
        float e0v = expf(gs[0] - m), e1v = expf(gs[1] - m),
              e2v = expf(gs[2] - m), e3v = expf(gs[3] - m);
        float inv = 1.0f / (e0v + e1v + e2v + e3v);
        // 4 threads write 4 distinct slots; read after one more barrier
        hs[tid] = expf(gs[tid] - m) * inv;
    }
    __syncthreads();

    const float g0 = hs[0], g1 = hs[1], g2 = hs[2], g3 = hs[3];
    float v[4];
    #pragma unroll
    for (int k = 0; k < 4; k++)
        v[k] = g0 * wa[k].x + g1 * wa[k].y + g2 * wa[k].z + g3 * wa[k].w;
    *(float4*)(&g_At[b][e0]) = make_float4(v[0], v[1], v[2], v[3]);

    #pragma unroll
    for (int k = 0; k < 4; k++)
        v[k] = SCALING * (g0 * wb[k].x + g1 * wb[k].y + g2 * wb[k].z + g3 * wb[k].w);
    *(float4*)(&g_Bm[b][e0]) = make_float4(v[0], v[1], v[2], v[3]);
}

// ---------------------------------------------------------------------------
// Kernel 2 (fused main): out[b][s][:] = (x[b][s][:] @ A^T) @ (SCALING*B)
// 512 threads, thread owns dims [tid*4, tid*4+4). 16 warps/SM for latency
// hiding. A,B in registers (f32x2 packed). 4 rows/iter, one barrier/iter,
// double-buffered partials, warp-replicated cross-warp reduce, shfl bcast.
// ---------------------------------------------------------------------------
__global__ __launch_bounds__(512, 1) void k_main(
    const float* __restrict__ x, float* __restrict__ out)
{
    const int b = blockIdx.y;
    const int tid = threadIdx.x;
    const int warp = tid >> 5, lane = tid & 31;
    const int d0 = tid * 4;

    // A packed: a2[j][rp] = { At[d0+j][rp], At[d0+j][rp+4] },  j=0..3, rp=0..3
    u64 a2[4][4];
    {
        const float* At = g_At[b];
        #pragma unroll
        for (int j = 0; j < 4; j++) {
            float4 lo = *(const float4*)(At + (size_t)(d0 + j) * 8);
            float4 hi = *(const float4*)(At + (size_t)(d0 + j) * 8 + 4);
            a2[j][0] = pk2(lo.x, hi.x); a2[j][1] = pk2(lo.y, hi.y);
            a2[j][2] = pk2(lo.z, hi.z); a2[j][3] = pk2(lo.w, hi.w);
        }
    }
    // B packed (pre-scaled): b2r[r][jp] = { B[r][d0+jp], B[r][d0+jp+2] }
    u64 b2r[8][2];
    {
        const float* Bm = g_Bm[b];
        #pragma unroll
        for (int r = 0; r < 8; r++) {
            float4 v4 = *(const float4*)(Bm + (size_t)r * DOUT + d0);
            b2r[r][0] = pk2(v4.x, v4.z);
            b2r[r][1] = pk2(v4.y, v4.w);
        }
    }

    __shared__ float part[2][16][32];

    const float* xb = x + (size_t)b * SEQ * DIN;
    float* ob = out + (size_t)b * SEQ * DOUT;
    const int step = gridDim.x;

    float4 xv[4];
    int q = blockIdx.x;
    {
        const int s = q * 4;
        #pragma unroll
        for (int rr = 0; rr < 4; rr++)
            xv[rr] = __ldcs((const float4*)(xb + (size_t)(s + rr) * DIN + d0));
    }

    int buf = 0;
    for (; q < SEQ / 4; q += step, buf ^= 1) {
        const int s = q * 4;

        // ---- phase 1: xa accumulation, packed over (r, r+4) ----
        u64 acc2[4][4];
        #pragma unroll
        for (int rr = 0; rr < 4; rr++)
            #pragma unroll
            for (int rp = 0; rp < 4; rp++) acc2[rr][rp] = 0ull;

        #pragma unroll
        for (int rr = 0; rr < 4; rr++) {
            const float* xr = (const float*)&xv[rr];
            #pragma unroll
            for (int j = 0; j < 4; j++) {
                u64 xj2 = rep2(xr[j]);
                #pragma unroll
                for (int rp = 0; rp < 4; rp++)
                    acc2[rr][rp] = ffma2(xj2, a2[j][rp], acc2[rr][rp]);
            }
        }

        // prefetch next iteration's rows (xv dead now)
        const int qn = q + step;
        if (qn < SEQ / 4) {
            const int sn = qn * 4;
            #pragma unroll
            for (int rr = 0; rr < 4; rr++)
                xv[rr] = __ldcs((const float4*)(xb + (size_t)(sn + rr) * DIN + d0));
        }

        // unpack: acc[rr*8 + r]
        float acc[32];
        #pragma unroll
        for (int rr = 0; rr < 4; rr++)
            #pragma unroll
            for (int rp = 0; rp < 4; rp++)
                upk2(acc2[rr][rp], acc[rr * 8 + rp], acc[rr * 8 + rp + 4]);

        // multi-value butterfly: lane l ends with warp-total of value l
        #pragma unroll
        for (int off = 16; off >= 1; off >>= 1) {
            const bool up = (lane & off) != 0;
            #pragma unroll
            for (int i = 0; i < off; i++) {
                float send = up ? acc[i] : acc[off + i];
                float recv = __shfl_xor_sync(0xffffffffu, send, off);
                acc[i] = (up ? acc[off + i] : acc[i]) + recv;
            }
        }

        part[buf][warp][lane] = acc[0];
        __syncthreads();

        // warp-replicated cross-warp sum: lane l of EVERY warp gets xa[l]
        float xa = part[buf][0][lane];
        #pragma unroll
        for (int w = 1; w < 16; w++) xa += part[buf][w][lane];

        // ---- phase 2: out rows; xa broadcast via shfl ----
        #pragma unroll
        for (int rr = 0; rr < 4; rr++) {
            u64 o2[2];
            o2[0] = 0ull; o2[1] = 0ull;
            #pragma unroll
            for (int r = 0; r < 8; r++) {
                float xs = __shfl_sync(0xffffffffu, xa, rr * 8 + r);
                u64 xs2 = rep2(xs);
                o2[0] = ffma2(xs2, b2r[r][0], o2[0]);
                o2[1] = ffma2(xs2, b2r[r][1], o2[1]);
            }
            float o0, o1, o2s, o3;
            upk2(o2[0], o0, o2s);
            upk2(o2[1], o1, o3);
            __stcs((float4*)(ob + (size_t)(s + rr) * DOUT + d0),
                   make_float4(o0, o1, o2s, o3));
        }
    }
}

// ---------------------------------------------------------------------------
extern "C" void kernel_launch(void* const* d_in, const int* in_sizes, int n_in,
                              void* d_out, int out_size)
{
    const float* x     = (const float*)d_in[0];
    const float* ctr   = (const float*)d_in[1];
    const float* gamma = (const float*)d_in[2];
    const float* beta  = (const float*)d_in[3];
    const float* W1    = (const float*)d_in[4];
    const float* b1    = (const float*)d_in[5];
    const float* W2    = (const float*)d_in[6];
    const float* b2    = (const float*)d_in[7];
    const float* Wa    = (const float*)d_in[8];
    const float* Wb    = (const float*)d_in[9];
    float* out = (float*)d_out;

    k_fill<<<dim3(16, 8), 256>>>(ctr, gamma, beta, W1, b1, W2, b2, Wa, Wb);
    k_main<<<dim3(18, 8), 512>>>(x, out);
}